// round 1
// baseline (speedup 1.0000x reference)
#include <cuda_runtime.h>
#include <math.h>

#define LROWS 128
#define EDIM 768
#define BKC 32
#define NCHUNK 24          // 768/32
#define THREADS 256

__device__ __forceinline__ unsigned long long pk2(float lo, float hi) {
    unsigned long long r;
    asm("mov.b64 %0, {%1, %2};" : "=l"(r) : "f"(lo), "f"(hi));
    return r;
}
__device__ __forceinline__ unsigned long long fma2(unsigned long long a,
                                                   unsigned long long b,
                                                   unsigned long long c) {
    unsigned long long d;
    asm("fma.rn.f32x2 %0, %1, %2, %3;" : "=l"(d) : "l"(a), "l"(b), "l"(c));
    return d;
}
__device__ __forceinline__ float2 up2(unsigned long long v) {
    float lo, hi;
    asm("mov.b64 {%0, %1}, %2;" : "=f"(lo), "=f"(hi) : "l"(v));
    return make_float2(lo, hi);
}

// dynamic smem layout (floats):
//   uni   [0, 16384)   : phase1 w0 staging (7680) | GEMM double buffers (16384) | argmax red (4096)
//   p_c   [16384, +640)
//   p_e   [+640)
//   inv_en[+128)
#define SMEM_FLOATS (16384 + 640 + 640 + 128)

__global__ __launch_bounds__(THREADS)
void som_mlp_kernel(const float* __restrict__ ctx,
                    const float* __restrict__ w0, const float* __restrict__ b0,
                    const float* __restrict__ w1, const float* __restrict__ b1,
                    const float* __restrict__ w2, const float* __restrict__ b2,
                    const float* __restrict__ w3, const float* __restrict__ b3,
                    const float* __restrict__ w4, const float* __restrict__ b4,
                    const float* __restrict__ w5, const float* __restrict__ b5,
                    const float* __restrict__ w6, const float* __restrict__ b6,
                    float* __restrict__ out)
{
    extern __shared__ float sm[];
    float* uni    = sm;
    float* p_c    = sm + 16384;
    float* p_e    = p_c + 640;
    float* inv_en = p_e + 640;

    const int tid  = threadIdx.x;
    const int lane = tid & 31;
    const int wid  = tid >> 5;
    const int p    = blockIdx.x;

    const float* Cb = ctx + (size_t)p * (2 * LROWS * EDIM);
    const float* Eb = Cb + LROWS * EDIM;

    // ---------- phase 0: stage w0 (5 x 1536) into smem ----------
    {
        const float4* src = (const float4*)w0;
        float4*       dst = (float4*)uni;
        for (int f = tid; f < (5 * 2 * EDIM) / 4; f += THREADS) dst[f] = src[f];
    }
    __syncthreads();

    // ---------- phase 1: row norms + first-layer projections ----------
    // 256 rows total (128 ctx + 128 ent), one row per warp per step.
    for (int g = wid; g < 256; g += 8) {
        const bool  isC  = (g < 128);
        const int   row  = g & 127;
        const float* base = (isC ? Cb : Eb) + row * EDIM;
        const float* wb   = uni + (isC ? 0 : EDIM);
        float sq = 0.f, d0 = 0.f, d1 = 0.f, d2 = 0.f, d3 = 0.f, d4 = 0.f;
        #pragma unroll
        for (int e = 0; e < EDIM; e += 128) {
            const int o = e + lane * 4;
            float4 x = *(const float4*)(base + o);
            sq += x.x * x.x + x.y * x.y + x.z * x.z + x.w * x.w;
            float4 w;
            w = *(const float4*)(wb + 0 * 1536 + o); d0 += x.x*w.x + x.y*w.y + x.z*w.z + x.w*w.w;
            w = *(const float4*)(wb + 1 * 1536 + o); d1 += x.x*w.x + x.y*w.y + x.z*w.z + x.w*w.w;
            w = *(const float4*)(wb + 2 * 1536 + o); d2 += x.x*w.x + x.y*w.y + x.z*w.z + x.w*w.w;
            w = *(const float4*)(wb + 3 * 1536 + o); d3 += x.x*w.x + x.y*w.y + x.z*w.z + x.w*w.w;
            w = *(const float4*)(wb + 4 * 1536 + o); d4 += x.x*w.x + x.y*w.y + x.z*w.z + x.w*w.w;
        }
        #pragma unroll
        for (int off = 16; off; off >>= 1) {
            sq += __shfl_xor_sync(0xffffffffu, sq, off);
            d0 += __shfl_xor_sync(0xffffffffu, d0, off);
            d1 += __shfl_xor_sync(0xffffffffu, d1, off);
            d2 += __shfl_xor_sync(0xffffffffu, d2, off);
            d3 += __shfl_xor_sync(0xffffffffu, d3, off);
            d4 += __shfl_xor_sync(0xffffffffu, d4, off);
        }
        if (lane == 0) {
            float inv = rsqrtf(sq);
            float* dst = isC ? (p_c + row * 5) : (p_e + row * 5);
            dst[0] = d0 * inv; dst[1] = d1 * inv; dst[2] = d2 * inv;
            dst[3] = d3 * inv; dst[4] = d4 * inv;
            if (!isC) inv_en[row] = inv;
        }
    }
    __syncthreads();

    // ---------- phase 2: 128x128x768 fp32 GEMM (D = C . E^T), FFMA2 ----------
    const int tx = tid & 15;      // col group (8 cols each)
    const int ty = tid >> 4;      // row group (8 rows each)

    unsigned long long acc[8][4];
    #pragma unroll
    for (int i = 0; i < 8; ++i)
        #pragma unroll
        for (int j = 0; j < 4; ++j) acc[i][j] = 0ull;

    float4 rA[4], rB[4];

    // prefetch chunk 0
    #pragma unroll
    for (int it = 0; it < 4; ++it) {
        int f = tid + 256 * it;
        int row = f >> 3, kq = f & 7;
        rA[it] = *(const float4*)(Cb + row * EDIM + kq * 4);
        rB[it] = *(const float4*)(Eb + row * EDIM + kq * 4);
    }
    // store chunk 0 -> buffer 0 (transpose to k-major with XOR swizzle)
    {
        float* Ab = uni;            // buf0 A
        float* Bb = uni + 4096;     // buf0 B
        #pragma unroll
        for (int it = 0; it < 4; ++it) {
            int f = tid + 256 * it;
            int row = f >> 3, kq = f & 7;
            int g = row >> 2, pos = row & 3;
            int base = (((g ^ kq) << 2) | pos);
            const float* av = (const float*)&rA[it];
            const float* bv = (const float*)&rB[it];
            #pragma unroll
            for (int i = 0; i < 4; ++i) {
                int idx = (kq * 4 + i) * 128 + base;
                Ab[idx] = av[i];
                Bb[idx] = bv[i];
            }
        }
    }
    __syncthreads();

    const int ga0 = ty * 2, ga1 = ty * 2 + 1;
    const int gb0 = tx * 2, gb1 = tx * 2 + 1;

    for (int kc = 0; kc < NCHUNK; ++kc) {
        // prefetch next chunk into registers (latency overlaps compute)
        if (kc + 1 < NCHUNK) {
            const int ko = (kc + 1) * BKC;
            #pragma unroll
            for (int it = 0; it < 4; ++it) {
                int f = tid + 256 * it;
                int row = f >> 3, kq = f & 7;
                rA[it] = *(const float4*)(Cb + row * EDIM + ko + kq * 4);
                rB[it] = *(const float4*)(Eb + row * EDIM + ko + kq * 4);
            }
        }
        // compute current chunk
        {
            const float* Ab = uni + (kc & 1) * 8192;
            const float* Bb = Ab + 4096;
            #pragma unroll 8
            for (int k = 0; k < BKC; ++k) {
                const int kq = k >> 2;
                const int ro = k * 128;
                float4 a0 = *(const float4*)(Ab + ro + ((ga0 ^ kq) << 2));
                float4 a1 = *(const float4*)(Ab + ro + ((ga1 ^ kq) << 2));
                float4 bv0 = *(const float4*)(Bb + ro + ((gb0 ^ kq) << 2));
                float4 bv1 = *(const float4*)(Bb + ro + ((gb1 ^ kq) << 2));
                unsigned long long bb0 = pk2(bv0.x, bv0.y);
                unsigned long long bb1 = pk2(bv0.z, bv0.w);
                unsigned long long bb2 = pk2(bv1.x, bv1.y);
                unsigned long long bb3 = pk2(bv1.z, bv1.w);
                float av[8] = {a0.x, a0.y, a0.z, a0.w, a1.x, a1.y, a1.z, a1.w};
                #pragma unroll
                for (int i = 0; i < 8; ++i) {
                    unsigned long long ad = pk2(av[i], av[i]);
                    acc[i][0] = fma2(ad, bb0, acc[i][0]);
                    acc[i][1] = fma2(ad, bb1, acc[i][1]);
                    acc[i][2] = fma2(ad, bb2, acc[i][2]);
                    acc[i][3] = fma2(ad, bb3, acc[i][3]);
                }
            }
        }
        __syncthreads();
        if (kc + 1 < NCHUNK) {
            float* Ab = uni + ((kc + 1) & 1) * 8192;
            float* Bb = Ab + 4096;
            #pragma unroll
            for (int it = 0; it < 4; ++it) {
                int f = tid + 256 * it;
                int row = f >> 3, kq = f & 7;
                int g = row >> 2, pos = row & 3;
                int base = (((g ^ kq) << 2) | pos);
                const float* av = (const float*)&rA[it];
                const float* bv = (const float*)&rB[it];
                #pragma unroll
                for (int i = 0; i < 4; ++i) {
                    int idx = (kq * 4 + i) * 128 + base;
                    Ab[idx] = av[i];
                    Bb[idx] = bv[i];
                }
            }
            __syncthreads();
        }
    }

    // ---------- phase 3: scaled argmax over columns ----------
    // (inv_cn factor dropped: positive per-row constant, argmax-invariant)
    float2* red = (float2*)uni;   // [128][16], write-swizzled to dodge bank conflicts
    #pragma unroll
    for (int i = 0; i < 8; ++i) {
        const int row = ty * 8 + i;
        float best = -3.402823466e38f;
        int   bidx = 0;
        #pragma unroll
        for (int jp = 0; jp < 4; ++jp) {
            float2 v = up2(acc[i][jp]);
            int c0 = tx * 8 + jp * 2;
            float s0 = v.x * inv_en[c0];
            float s1 = v.y * inv_en[c0 + 1];
            if (s0 > best) { best = s0; bidx = c0; }
            if (s1 > best) { best = s1; bidx = c0 + 1; }
        }
        red[row * 16 + ((tx + row) & 15)] = make_float2(best, __int_as_float(bidx));
    }
    __syncthreads();

    // ---------- phase 4: per-row MLP + block sum ----------
    float partial = 0.f;
    if (tid < 128) {
        const int l = tid;
        float best = -3.402823466e38f;
        int   bidx = 0;
        #pragma unroll
        for (int t = 0; t < 16; ++t) {      // ascending col-block order: matches argmax tie-break
            float2 v = red[l * 16 + ((t + l) & 15)];
            if (v.x > best) { best = v.x; bidx = __float_as_int(v.y); }
        }
        float h0[5];
        #pragma unroll
        for (int j = 0; j < 5; ++j)
            h0[j] = tanhf(p_c[l * 5 + j] + p_e[bidx * 5 + j] + __ldg(b0 + j));
        float s0 = __ldg(b1 + 0), s1 = __ldg(b1 + 1);
        #pragma unroll
        for (int j = 0; j < 5; ++j) {
            s0 += __ldg(w1 + j)     * h0[j];
            s1 += __ldg(w1 + 5 + j) * h0[j];
        }
        float h10 = tanhf(s0), h11 = tanhf(s1);
        float z = tanhf(__ldg(w2) * h10 + __ldg(w2 + 1) * h11 + __ldg(b2));
        z = tanhf(__ldg(w3) * z + __ldg(b3));
        z = tanhf(__ldg(w4) * z + __ldg(b4));
        z = tanhf(__ldg(w5) * z + __ldg(b5));
        partial = __ldg(w6) * z + __ldg(b6);
    }
    #pragma unroll
    for (int off = 16; off; off >>= 1)
        partial += __shfl_xor_sync(0xffffffffu, partial, off);
    __shared__ float ssum[8];
    if (lane == 0) ssum[wid] = partial;
    __syncthreads();
    if (tid == 0) {
        float t = 0.f;
        #pragma unroll
        for (int w = 0; w < 8; ++w) t += ssum[w];
        out[p] = t;
    }
}

extern "C" void kernel_launch(void* const* d_in, const int* in_sizes, int n_in,
                              void* d_out, int out_size)
{
    const float* ctx = (const float*)d_in[0];
    const float* w0 = (const float*)d_in[1];  const float* b0 = (const float*)d_in[2];
    const float* w1 = (const float*)d_in[3];  const float* b1 = (const float*)d_in[4];
    const float* w2 = (const float*)d_in[5];  const float* b2 = (const float*)d_in[6];
    const float* w3 = (const float*)d_in[7];  const float* b3 = (const float*)d_in[8];
    const float* w4 = (const float*)d_in[9];  const float* b4 = (const float*)d_in[10];
    const float* w5 = (const float*)d_in[11]; const float* b5 = (const float*)d_in[12];
    const float* w6 = (const float*)d_in[13]; const float* b6 = (const float*)d_in[14];
    float* out = (float*)d_out;

    const int smem_bytes = SMEM_FLOATS * 4;   // 71168
    cudaFuncSetAttribute(som_mlp_kernel,
                         cudaFuncAttributeMaxDynamicSharedMemorySize, smem_bytes);
    som_mlp_kernel<<<1024, THREADS, smem_bytes>>>(
        ctx, w0, b0, w1, b1, w2, b2, w3, b3, w4, b4, w5, b5, w6, b6, out);
}

// round 2
// speedup vs baseline: 1.4228x; 1.4228x over previous
#include <cuda_runtime.h>
#include <math.h>

#define LROWS 128
#define EDIM 768
#define BKC 16
#define NCHUNK 48          // 768/16
#define THREADS 256

__device__ __forceinline__ unsigned long long pk2(float lo, float hi) {
    unsigned long long r;
    asm("mov.b64 %0, {%1, %2};" : "=l"(r) : "f"(lo), "f"(hi));
    return r;
}
__device__ __forceinline__ unsigned long long fma2(unsigned long long a,
                                                   unsigned long long b,
                                                   unsigned long long c) {
    unsigned long long d;
    asm("fma.rn.f32x2 %0, %1, %2, %3;" : "=l"(d) : "l"(a), "l"(b), "l"(c));
    return d;
}
__device__ __forceinline__ float2 up2(unsigned long long v) {
    float lo, hi;
    asm("mov.b64 {%0, %1}, %2;" : "=f"(lo), "=f"(hi) : "l"(v));
    return make_float2(lo, hi);
}

// dynamic smem (floats):
//   uni   [0, 8192)  : phase0/1 w0 staging (7680) | GEMM double buffers (8192) | argmax red (8192)
//   p_c   [8192, +640)
//   p_e   [+640)
//   inv_en[+128)
#define SMEM_FLOATS (8192 + 640 + 640 + 128)

__global__ __launch_bounds__(THREADS, 2)
void som_mlp_kernel(const float* __restrict__ ctx,
                    const float* __restrict__ w0, const float* __restrict__ b0,
                    const float* __restrict__ w1, const float* __restrict__ b1,
                    const float* __restrict__ w2, const float* __restrict__ b2,
                    const float* __restrict__ w3, const float* __restrict__ b3,
                    const float* __restrict__ w4, const float* __restrict__ b4,
                    const float* __restrict__ w5, const float* __restrict__ b5,
                    const float* __restrict__ w6, const float* __restrict__ b6,
                    float* __restrict__ out)
{
    extern __shared__ float sm[];
    float* uni    = sm;
    float* p_c    = sm + 8192;
    float* p_e    = p_c + 640;
    float* inv_en = p_e + 640;

    const int tid  = threadIdx.x;
    const int lane = tid & 31;
    const int wid  = tid >> 5;
    const int p    = blockIdx.x;

    const float* Cb = ctx + (size_t)p * (2 * LROWS * EDIM);
    const float* Eb = Cb + LROWS * EDIM;

    // ---------- phase 0: stage w0 (5 x 1536) into smem ----------
    {
        const float4* src = (const float4*)w0;
        float4*       dst = (float4*)uni;
        for (int f = tid; f < (5 * 2 * EDIM) / 4; f += THREADS) dst[f] = src[f];
    }
    __syncthreads();

    // ---------- phase 1: row norms + first-layer projections ----------
    for (int g = wid; g < 256; g += 8) {
        const bool  isC  = (g < 128);
        const int   row  = g & 127;
        const float* base = (isC ? Cb : Eb) + row * EDIM;
        const float* wb   = uni + (isC ? 0 : EDIM);
        float sq = 0.f, d0 = 0.f, d1 = 0.f, d2 = 0.f, d3 = 0.f, d4 = 0.f;
        #pragma unroll
        for (int e = 0; e < EDIM; e += 128) {
            const int o = e + lane * 4;
            float4 x = *(const float4*)(base + o);
            sq += x.x * x.x + x.y * x.y + x.z * x.z + x.w * x.w;
            float4 w;
            w = *(const float4*)(wb + 0 * 1536 + o); d0 += x.x*w.x + x.y*w.y + x.z*w.z + x.w*w.w;
            w = *(const float4*)(wb + 1 * 1536 + o); d1 += x.x*w.x + x.y*w.y + x.z*w.z + x.w*w.w;
            w = *(const float4*)(wb + 2 * 1536 + o); d2 += x.x*w.x + x.y*w.y + x.z*w.z + x.w*w.w;
            w = *(const float4*)(wb + 3 * 1536 + o); d3 += x.x*w.x + x.y*w.y + x.z*w.z + x.w*w.w;
            w = *(const float4*)(wb + 4 * 1536 + o); d4 += x.x*w.x + x.y*w.y + x.z*w.z + x.w*w.w;
        }
        #pragma unroll
        for (int off = 16; off; off >>= 1) {
            sq += __shfl_xor_sync(0xffffffffu, sq, off);
            d0 += __shfl_xor_sync(0xffffffffu, d0, off);
            d1 += __shfl_xor_sync(0xffffffffu, d1, off);
            d2 += __shfl_xor_sync(0xffffffffu, d2, off);
            d3 += __shfl_xor_sync(0xffffffffu, d3, off);
            d4 += __shfl_xor_sync(0xffffffffu, d4, off);
        }
        if (lane == 0) {
            float inv = rsqrtf(sq);
            float* dst = isC ? (p_c + row * 5) : (p_e + row * 5);
            dst[0] = d0 * inv; dst[1] = d1 * inv; dst[2] = d2 * inv;
            dst[3] = d3 * inv; dst[4] = d4 * inv;
            if (!isC) inv_en[row] = inv;
        }
    }
    __syncthreads();

    // ---------- phase 2: 128x128x768 fp32 GEMM (D = C . E^T), FFMA2 ----------
    // Thread (tx,ty): rows {4ty..4ty+3, 64+4ty..+3}, cols {4tx..4tx+3, 64+4tx..+3}
    const int tx = tid & 15;
    const int ty = tid >> 4;

    unsigned long long acc[8][4];
    #pragma unroll
    for (int i = 0; i < 8; ++i)
        #pragma unroll
        for (int j = 0; j < 4; ++j) acc[i][j] = 0ull;

    float4 rA[2], rB[2];

    // prefetch chunk 0
    #pragma unroll
    for (int it = 0; it < 2; ++it) {
        int f = tid + 256 * it;
        int row = f >> 2, kq = f & 3;
        rA[it] = *(const float4*)(Cb + row * EDIM + kq * 4);
        rB[it] = *(const float4*)(Eb + row * EDIM + kq * 4);
    }
    // store chunk 0 -> buffer 0 (transpose to k-major with XOR swizzle)
    {
        float* Ab = uni;
        float* Bb = uni + 2048;
        #pragma unroll
        for (int it = 0; it < 2; ++it) {
            int f = tid + 256 * it;
            int row = f >> 2, kq = f & 3;
            int g = row >> 2, pos = row & 3;
            int base = (((g ^ kq) << 2) | pos);
            const float* av = (const float*)&rA[it];
            const float* bv = (const float*)&rB[it];
            #pragma unroll
            for (int i = 0; i < 4; ++i) {
                int idx = (kq * 4 + i) * 128 + base;
                Ab[idx] = av[i];
                Bb[idx] = bv[i];
            }
        }
    }
    __syncthreads();

    for (int kc = 0; kc < NCHUNK; ++kc) {
        if (kc + 1 < NCHUNK) {
            const int ko = (kc + 1) * BKC;
            #pragma unroll
            for (int it = 0; it < 2; ++it) {
                int f = tid + 256 * it;
                int row = f >> 2, kq = f & 3;
                rA[it] = *(const float4*)(Cb + row * EDIM + ko + kq * 4);
                rB[it] = *(const float4*)(Eb + row * EDIM + ko + kq * 4);
            }
        }
        {
            const float* Ab = uni + (kc & 1) * 4096;
            const float* Bb = Ab + 2048;
            #pragma unroll 8
            for (int k = 0; k < BKC; ++k) {
                const int kq = k >> 2;
                const int ro = k * 128;
                // conflict-free: 8-lane phase groups hit distinct (tx^kq) 16B slots
                float4 a0  = *(const float4*)(Ab + ro + ((ty ^ kq) << 2));
                float4 a1  = *(const float4*)(Ab + ro + (((ty + 16) ^ kq) << 2));
                float4 bv0 = *(const float4*)(Bb + ro + ((tx ^ kq) << 2));
                float4 bv1 = *(const float4*)(Bb + ro + (((tx + 16) ^ kq) << 2));
                unsigned long long bb0 = pk2(bv0.x, bv0.y);
                unsigned long long bb1 = pk2(bv0.z, bv0.w);
                unsigned long long bb2 = pk2(bv1.x, bv1.y);
                unsigned long long bb3 = pk2(bv1.z, bv1.w);
                float av[8] = {a0.x, a0.y, a0.z, a0.w, a1.x, a1.y, a1.z, a1.w};
                #pragma unroll
                for (int i = 0; i < 8; ++i) {
                    unsigned long long ad = pk2(av[i], av[i]);
                    acc[i][0] = fma2(ad, bb0, acc[i][0]);
                    acc[i][1] = fma2(ad, bb1, acc[i][1]);
                    acc[i][2] = fma2(ad, bb2, acc[i][2]);
                    acc[i][3] = fma2(ad, bb3, acc[i][3]);
                }
            }
        }
        __syncthreads();
        if (kc + 1 < NCHUNK) {
            float* Ab = uni + ((kc + 1) & 1) * 4096;
            float* Bb = Ab + 2048;
            #pragma unroll
            for (int it = 0; it < 2; ++it) {
                int f = tid + 256 * it;
                int row = f >> 2, kq = f & 3;
                int g = row >> 2, pos = row & 3;
                int base = (((g ^ kq) << 2) | pos);
                const float* av = (const float*)&rA[it];
                const float* bv = (const float*)&rB[it];
                #pragma unroll
                for (int i = 0; i < 4; ++i) {
                    int idx = (kq * 4 + i) * 128 + base;
                    Ab[idx] = av[i];
                    Bb[idx] = bv[i];
                }
            }
            __syncthreads();
        }
    }

    // ---------- phase 3: scaled argmax over columns ----------
    // Two slots per thread/row: slot tx covers cols [4tx,4tx+3] (lo half),
    // slot 16+tx covers cols [64+4tx, 64+4tx+3] (hi half). Logical slot order
    // 0..31 is strictly ascending in column index -> preserves argmax tie-break.
    float2* red = (float2*)uni;   // [128][32] float2
    #pragma unroll
    for (int i = 0; i < 8; ++i) {
        const int row = (i < 4) ? (ty * 4 + i) : (64 + ty * 4 + (i - 4));
        float bl = -3.402823466e38f; int il = 0;
        float bh = -3.402823466e38f; int ih = 0;
        #pragma unroll
        for (int jp = 0; jp < 2; ++jp) {
            float2 v = up2(acc[i][jp]);
            int c0 = 4 * tx + jp * 2;
            float s0 = v.x * inv_en[c0];
            float s1 = v.y * inv_en[c0 + 1];
            if (s0 > bl) { bl = s0; il = c0; }
            if (s1 > bl) { bl = s1; il = c0 + 1; }
        }
        #pragma unroll
        for (int jp = 2; jp < 4; ++jp) {
            float2 v = up2(acc[i][jp]);
            int c0 = 64 + 4 * tx + (jp - 2) * 2;
            float s0 = v.x * inv_en[c0];
            float s1 = v.y * inv_en[c0 + 1];
            if (s0 > bh) { bh = s0; ih = c0; }
            if (s1 > bh) { bh = s1; ih = c0 + 1; }
        }
        red[row * 32 + ((tx + row) & 31)]        = make_float2(bl, __int_as_float(il));
        red[row * 32 + (((16 + tx) + row) & 31)] = make_float2(bh, __int_as_float(ih));
    }
    __syncthreads();

    // ---------- phase 4: per-row MLP + block sum ----------
    float partial = 0.f;
    if (tid < 128) {
        const int l = tid;
        float best = -3.402823466e38f;
        int   bidx = 0;
        #pragma unroll
        for (int t = 0; t < 32; ++t) {   // ascending logical slot = ascending cols
            float2 v = red[l * 32 + ((t + l) & 31)];
            if (v.x > best) { best = v.x; bidx = __float_as_int(v.y); }
        }
        float h0[5];
        #pragma unroll
        for (int j = 0; j < 5; ++j)
            h0[j] = tanhf(p_c[l * 5 + j] + p_e[bidx * 5 + j] + __ldg(b0 + j));
        float s0 = __ldg(b1 + 0), s1 = __ldg(b1 + 1);
        #pragma unroll
        for (int j = 0; j < 5; ++j) {
            s0 += __ldg(w1 + j)     * h0[j];
            s1 += __ldg(w1 + 5 + j) * h0[j];
        }
        float h10 = tanhf(s0), h11 = tanhf(s1);
        float z = tanhf(__ldg(w2) * h10 + __ldg(w2 + 1) * h11 + __ldg(b2));
        z = tanhf(__ldg(w3) * z + __ldg(b3));
        z = tanhf(__ldg(w4) * z + __ldg(b4));
        z = tanhf(__ldg(w5) * z + __ldg(b5));
        partial = __ldg(w6) * z + __ldg(b6);
    }
    #pragma unroll
    for (int off = 16; off; off >>= 1)
        partial += __shfl_xor_sync(0xffffffffu, partial, off);
    __shared__ float ssum[8];
    if (lane == 0) ssum[wid] = partial;
    __syncthreads();
    if (tid == 0) {
        float t = 0.f;
        #pragma unroll
        for (int w = 0; w < 8; ++w) t += ssum[w];
        out[p] = t;
    }
}

extern "C" void kernel_launch(void* const* d_in, const int* in_sizes, int n_in,
                              void* d_out, int out_size)
{
    const float* ctx = (const float*)d_in[0];
    const float* w0 = (const float*)d_in[1];  const float* b0 = (const float*)d_in[2];
    const float* w1 = (const float*)d_in[3];  const float* b1 = (const float*)d_in[4];
    const float* w2 = (const float*)d_in[5];  const float* b2 = (const float*)d_in[6];
    const float* w3 = (const float*)d_in[7];  const float* b3 = (const float*)d_in[8];
    const float* w4 = (const float*)d_in[9];  const float* b4 = (const float*)d_in[10];
    const float* w5 = (const float*)d_in[11]; const float* b5 = (const float*)d_in[12];
    const float* w6 = (const float*)d_in[13]; const float* b6 = (const float*)d_in[14];
    float* out = (float*)d_out;

    const int smem_bytes = SMEM_FLOATS * 4;   // 38400
    cudaFuncSetAttribute(som_mlp_kernel,
                         cudaFuncAttributeMaxDynamicSharedMemorySize, smem_bytes);
    som_mlp_kernel<<<1024, THREADS, smem_bytes>>>(
        ctx, w0, b0, w1, b1, w2, b2, w3, b3, w4, b4, w5, b5, w6, b6, out);
}

// round 3
// speedup vs baseline: 1.5510x; 1.0901x over previous
#include <cuda_runtime.h>
#include <math.h>

#define LROWS 128
#define EDIM 768
#define BKC 16
#define NCHUNK 48          // 768/16
#define THREADS 256

__device__ __forceinline__ unsigned long long pk2(float lo, float hi) {
    unsigned long long r;
    asm("mov.b64 %0, {%1, %2};" : "=l"(r) : "f"(lo), "f"(hi));
    return r;
}
__device__ __forceinline__ unsigned long long fma2(unsigned long long a,
                                                   unsigned long long b,
                                                   unsigned long long c) {
    unsigned long long d;
    asm("fma.rn.f32x2 %0, %1, %2, %3;" : "=l"(d) : "l"(a), "l"(b), "l"(c));
    return d;
}
__device__ __forceinline__ float2 up2(unsigned long long v) {
    float lo, hi;
    asm("mov.b64 {%0, %1}, %2;" : "=f"(lo), "=f"(hi) : "l"(v));
    return make_float2(lo, hi);
}

// dynamic smem (floats):
//   uni   [0, 8192)  : phase0/1 w0 staging (7680) | GEMM double buffers (8192) | argmax red (8192)
//   p_c   [8192, +640)
//   p_e   [+640)
//   inv_en[+128)
#define SMEM_FLOATS (8192 + 640 + 640 + 128)

__global__ __launch_bounds__(THREADS, 2)
void som_mlp_kernel(const float* __restrict__ ctx,
                    const float* __restrict__ w0, const float* __restrict__ b0,
                    const float* __restrict__ w1, const float* __restrict__ b1,
                    const float* __restrict__ w2, const float* __restrict__ b2,
                    const float* __restrict__ w3, const float* __restrict__ b3,
                    const float* __restrict__ w4, const float* __restrict__ b4,
                    const float* __restrict__ w5, const float* __restrict__ b5,
                    const float* __restrict__ w6, const float* __restrict__ b6,
                    float* __restrict__ out)
{
    extern __shared__ float sm[];
    float* uni    = sm;
    float* p_c    = sm + 8192;
    float* p_e    = p_c + 640;
    float* inv_en = p_e + 640;

    const int tid  = threadIdx.x;
    const int lane = tid & 31;
    const int wid  = tid >> 5;
    const int p    = blockIdx.x;

    const float* Cb = ctx + (size_t)p * (2 * LROWS * EDIM);
    const float* Eb = Cb + LROWS * EDIM;

    // ---------- phase 0: stage w0 (5 x 1536) into smem ----------
    {
        const float4* src = (const float4*)w0;
        float4*       dst = (float4*)uni;
        for (int f = tid; f < (5 * 2 * EDIM) / 4; f += THREADS) dst[f] = src[f];
    }
    __syncthreads();

    // ---------- phase 1: row norms + first-layer projections ----------
    // Two rows per iteration: one set of w0 LDS serves both rows.
    for (int half = 0; half < 2; ++half) {
        const float* Xb   = half ? Eb : Cb;
        const int    woff = half ? EDIM : 0;
        for (int pr = wid; pr < 64; pr += 8) {
            const float* x0p = Xb + (2 * pr) * EDIM;
            const float* x1p = x0p + EDIM;
            float sq0 = 0.f, sq1 = 0.f;
            float d0[5] = {0,0,0,0,0}, d1[5] = {0,0,0,0,0};
            #pragma unroll
            for (int e = 0; e < EDIM; e += 128) {
                const int o = e + lane * 4;
                float4 x0 = *(const float4*)(x0p + o);
                float4 x1 = *(const float4*)(x1p + o);
                sq0 += x0.x*x0.x + x0.y*x0.y + x0.z*x0.z + x0.w*x0.w;
                sq1 += x1.x*x1.x + x1.y*x1.y + x1.z*x1.z + x1.w*x1.w;
                #pragma unroll
                for (int j = 0; j < 5; ++j) {
                    float4 w = *(const float4*)(uni + j * 1536 + woff + o);
                    d0[j] += x0.x*w.x + x0.y*w.y + x0.z*w.z + x0.w*w.w;
                    d1[j] += x1.x*w.x + x1.y*w.y + x1.z*w.z + x1.w*w.w;
                }
            }
            #pragma unroll
            for (int off = 16; off; off >>= 1) {
                sq0 += __shfl_xor_sync(0xffffffffu, sq0, off);
                sq1 += __shfl_xor_sync(0xffffffffu, sq1, off);
                #pragma unroll
                for (int j = 0; j < 5; ++j) {
                    d0[j] += __shfl_xor_sync(0xffffffffu, d0[j], off);
                    d1[j] += __shfl_xor_sync(0xffffffffu, d1[j], off);
                }
            }
            if (lane == 0) {
                const int r0 = 2 * pr, r1 = 2 * pr + 1;
                float inv0 = rsqrtf(sq0);
                float inv1 = rsqrtf(sq1);
                float* dst = half ? p_e : p_c;
                #pragma unroll
                for (int j = 0; j < 5; ++j) {
                    dst[r0 * 5 + j] = d0[j] * inv0;
                    dst[r1 * 5 + j] = d1[j] * inv1;
                }
                if (half) { inv_en[r0] = inv0; inv_en[r1] = inv1; }
            }
        }
    }
    __syncthreads();

    // ---------- phase 2: 128x128x768 fp32 GEMM (D = C . E^T), FFMA2 ----------
    // Thread (tx,ty): rows {4ty..4ty+3, 64+4ty..+3}, cols {4tx..4tx+3, 64+4tx..+3}
    const int tx = tid & 15;
    const int ty = tid >> 4;

    unsigned long long acc[8][4];
    #pragma unroll
    for (int i = 0; i < 8; ++i)
        #pragma unroll
        for (int j = 0; j < 4; ++j) acc[i][j] = 0ull;

    // global-load lane geometry (fixed per thread)
    const int gr0 = tid >> 2;            // row for fragment 0
    const int gr1 = (tid + 256) >> 2;    // row for fragment 1
    const int gkq = tid & 3;             // k-quad 0..3
    const int sb0 = ((((gr0 >> 2) ^ gkq) << 2) | (gr0 & 3));  // swizzled store base
    const int sb1 = ((((gr1 >> 2) ^ gkq) << 2) | (gr1 & 3));

    float4 rA[2], rB[2];

    // prologue: chunk 0 -> regs -> buf0; then prefetch chunk 1 -> regs
    rA[0] = *(const float4*)(Cb + gr0 * EDIM + gkq * 4);
    rA[1] = *(const float4*)(Cb + gr1 * EDIM + gkq * 4);
    rB[0] = *(const float4*)(Eb + gr0 * EDIM + gkq * 4);
    rB[1] = *(const float4*)(Eb + gr1 * EDIM + gkq * 4);
    {
        float* Ab = uni;
        float* Bb = uni + 2048;
        #pragma unroll
        for (int i = 0; i < 4; ++i) {
            Ab[(gkq * 4 + i) * 128 + sb0] = ((const float*)&rA[0])[i];
            Ab[(gkq * 4 + i) * 128 + sb1] = ((const float*)&rA[1])[i];
            Bb[(gkq * 4 + i) * 128 + sb0] = ((const float*)&rB[0])[i];
            Bb[(gkq * 4 + i) * 128 + sb1] = ((const float*)&rB[1])[i];
        }
    }
    __syncthreads();
    rA[0] = *(const float4*)(Cb + gr0 * EDIM + BKC + gkq * 4);
    rA[1] = *(const float4*)(Cb + gr1 * EDIM + BKC + gkq * 4);
    rB[0] = *(const float4*)(Eb + gr0 * EDIM + BKC + gkq * 4);
    rB[1] = *(const float4*)(Eb + gr1 * EDIM + BKC + gkq * 4);

    for (int kc = 0; kc < NCHUNK; ++kc) {
        // 1) store staged regs (chunk kc+1) into the idle buffer
        if (kc + 1 < NCHUNK) {
            float* Ab = uni + ((kc + 1) & 1) * 4096;
            float* Bb = Ab + 2048;
            #pragma unroll
            for (int i = 0; i < 4; ++i) {
                Ab[(gkq * 4 + i) * 128 + sb0] = ((const float*)&rA[0])[i];
                Ab[(gkq * 4 + i) * 128 + sb1] = ((const float*)&rA[1])[i];
                Bb[(gkq * 4 + i) * 128 + sb0] = ((const float*)&rB[0])[i];
                Bb[(gkq * 4 + i) * 128 + sb1] = ((const float*)&rB[1])[i];
            }
        }
        // 2) kick off global loads for chunk kc+2 (latency spans this chunk's math)
        if (kc + 2 < NCHUNK) {
            const int ko = (kc + 2) * BKC + gkq * 4;
            rA[0] = *(const float4*)(Cb + gr0 * EDIM + ko);
            rA[1] = *(const float4*)(Cb + gr1 * EDIM + ko);
            rB[0] = *(const float4*)(Eb + gr0 * EDIM + ko);
            rB[1] = *(const float4*)(Eb + gr1 * EDIM + ko);
        }
        // 3) compute current chunk
        {
            const float* Ab = uni + (kc & 1) * 4096;
            const float* Bb = Ab + 2048;
            #pragma unroll
            for (int k = 0; k < BKC; ++k) {
                const int kq = k >> 2;
                const int ro = k * 128;
                float4 a0  = *(const float4*)(Ab + ro + ((ty ^ kq) << 2));
                float4 a1  = *(const float4*)(Ab + ro + (((ty + 16) ^ kq) << 2));
                float4 bv0 = *(const float4*)(Bb + ro + ((tx ^ kq) << 2));
                float4 bv1 = *(const float4*)(Bb + ro + (((tx + 16) ^ kq) << 2));
                unsigned long long bb0 = pk2(bv0.x, bv0.y);
                unsigned long long bb1 = pk2(bv0.z, bv0.w);
                unsigned long long bb2 = pk2(bv1.x, bv1.y);
                unsigned long long bb3 = pk2(bv1.z, bv1.w);
                float av[8] = {a0.x, a0.y, a0.z, a0.w, a1.x, a1.y, a1.z, a1.w};
                #pragma unroll
                for (int i = 0; i < 8; ++i) {
                    unsigned long long ad = pk2(av[i], av[i]);
                    acc[i][0] = fma2(ad, bb0, acc[i][0]);
                    acc[i][1] = fma2(ad, bb1, acc[i][1]);
                    acc[i][2] = fma2(ad, bb2, acc[i][2]);
                    acc[i][3] = fma2(ad, bb3, acc[i][3]);
                }
            }
        }
        __syncthreads();
    }

    // ---------- phase 3: scaled argmax over columns ----------
    // Two slots per thread/row: slot tx covers cols [4tx,4tx+3] (lo half),
    // slot 16+tx covers cols [64+4tx, 64+4tx+3] (hi half). Logical slot order
    // 0..31 is strictly ascending in column index -> preserves argmax tie-break.
    float2* red = (float2*)uni;   // [128][32] float2
    #pragma unroll
    for (int i = 0; i < 8; ++i) {
        const int row = (i < 4) ? (ty * 4 + i) : (64 + ty * 4 + (i - 4));
        float bl = -3.402823466e38f; int il = 0;
        float bh = -3.402823466e38f; int ih = 0;
        #pragma unroll
        for (int jp = 0; jp < 2; ++jp) {
            float2 v = up2(acc[i][jp]);
            int c0 = 4 * tx + jp * 2;
            float s0 = v.x * inv_en[c0];
            float s1 = v.y * inv_en[c0 + 1];
            if (s0 > bl) { bl = s0; il = c0; }
            if (s1 > bl) { bl = s1; il = c0 + 1; }
        }
        #pragma unroll
        for (int jp = 2; jp < 4; ++jp) {
            float2 v = up2(acc[i][jp]);
            int c0 = 64 + 4 * tx + (jp - 2) * 2;
            float s0 = v.x * inv_en[c0];
            float s1 = v.y * inv_en[c0 + 1];
            if (s0 > bh) { bh = s0; ih = c0; }
            if (s1 > bh) { bh = s1; ih = c0 + 1; }
        }
        red[row * 32 + ((tx + row) & 31)]        = make_float2(bl, __int_as_float(il));
        red[row * 32 + (((16 + tx) + row) & 31)] = make_float2(bh, __int_as_float(ih));
    }
    __syncthreads();

    // ---------- phase 4: per-row MLP + block sum ----------
    float partial = 0.f;
    if (tid < 128) {
        const int l = tid;
        float best = -3.402823466e38f;
        int   bidx = 0;
        #pragma unroll
        for (int t = 0; t < 32; ++t) {   // ascending logical slot = ascending cols
            float2 v = red[l * 32 + ((t + l) & 31)];
            if (v.x > best) { best = v.x; bidx = __float_as_int(v.y); }
        }
        float h0[5];
        #pragma unroll
        for (int j = 0; j < 5; ++j)
            h0[j] = tanhf(p_c[l * 5 + j] + p_e[bidx * 5 + j] + __ldg(b0 + j));
        float s0 = __ldg(b1 + 0), s1 = __ldg(b1 + 1);
        #pragma unroll
        for (int j = 0; j < 5; ++j) {
            s0 += __ldg(w1 + j)     * h0[j];
            s1 += __ldg(w1 + 5 + j) * h0[j];
        }
        float h10 = tanhf(s0), h11 = tanhf(s1);
        float z = tanhf(__ldg(w2) * h10 + __ldg(w2 + 1) * h11 + __ldg(b2));
        z = tanhf(__ldg(w3) * z + __ldg(b3));
        z = tanhf(__ldg(w4) * z + __ldg(b4));
        z = tanhf(__ldg(w5) * z + __ldg(b5));
        partial = __ldg(w6) * z + __ldg(b6);
    }
    #pragma unroll
    for (int off = 16; off; off >>= 1)
        partial += __shfl_xor_sync(0xffffffffu, partial, off);
    __shared__ float ssum[8];
    if (lane == 0) ssum[wid] = partial;
    __syncthreads();
    if (tid == 0) {
        float t = 0.f;
        #pragma unroll
        for (int w = 0; w < 8; ++w) t += ssum[w];
        out[p] = t;
    }
}

extern "C" void kernel_launch(void* const* d_in, const int* in_sizes, int n_in,
                              void* d_out, int out_size)
{
    const float* ctx = (const float*)d_in[0];
    const float* w0 = (const float*)d_in[1];  const float* b0 = (const float*)d_in[2];
    const float* w1 = (const float*)d_in[3];  const float* b1 = (const float*)d_in[4];
    const float* w2 = (const float*)d_in[5];  const float* b2 = (const float*)d_in[6];
    const float* w3 = (const float*)d_in[7];  const float* b3 = (const float*)d_in[8];
    const float* w4 = (const float*)d_in[9];  const float* b4 = (const float*)d_in[10];
    const float* w5 = (const float*)d_in[11]; const float* b5 = (const float*)d_in[12];
    const float* w6 = (const float*)d_in[13]; const float* b6 = (const float*)d_in[14];
    float* out = (float*)d_out;

    const int smem_bytes = SMEM_FLOATS * 4;   // 38400
    cudaFuncSetAttribute(som_mlp_kernel,
                         cudaFuncAttributeMaxDynamicSharedMemorySize, smem_bytes);
    som_mlp_kernel<<<1024, THREADS, smem_bytes>>>(
        ctx, w0, b0, w1, b1, w2, b2, w3, b3, w4, b4, w5, b5, w6, b6, out);
}